// round 4
// baseline (speedup 1.0000x reference)
#include <cuda_runtime.h>
#include <stdint.h>
#include <math.h>

#define BATCH 4
#define SEQ   2048
#define NH    16
#define DHEAD 64
#define DMODEL 1024

// Scratch (allocation-free rule: __device__ globals)
__device__ float g_q[(size_t)BATCH*NH*SEQ*DHEAD];
__device__ float g_k[(size_t)BATCH*NH*SEQ*DHEAD];
__device__ float g_v[(size_t)BATCH*NH*SEQ*DHEAD];
__device__ float g_att[(size_t)BATCH*SEQ*DMODEL];

__device__ __forceinline__ unsigned f2tf(float f){
    unsigned u;
    asm("cvt.rna.tf32.f32 %0, %1;" : "=r"(u) : "f"(f));
    return u;
}

__device__ __forceinline__ uint32_t s2u(const void* p){
    return (uint32_t)__cvta_generic_to_shared(p);
}

__device__ __forceinline__ void ldsm4(unsigned r[4], uint32_t addr){
    asm volatile("ldmatrix.sync.aligned.m8n8.x4.shared.b16 {%0,%1,%2,%3}, [%4];"
        : "=r"(r[0]), "=r"(r[1]), "=r"(r[2]), "=r"(r[3]) : "r"(addr));
}

__device__ __forceinline__ void mma_tf32(float* d, const unsigned* a, const unsigned* b){
    asm volatile(
        "mma.sync.aligned.m16n8k8.row.col.f32.tf32.tf32.f32 "
        "{%0,%1,%2,%3},{%4,%5,%6,%7},{%8,%9},{%0,%1,%2,%3};\n"
        : "+f"(d[0]), "+f"(d[1]), "+f"(d[2]), "+f"(d[3])
        : "r"(a[0]), "r"(a[1]), "r"(a[2]), "r"(a[3]), "r"(b[0]), "r"(b[1]));
}

// ---------------------------------------------------------------------------
// tf32 GEMM core: C[128 x 64] = A[128 x K] * B[K x 64] + bias
// 256 threads, 8 warps (4m x 2n), warp tile 32x32, BK=32.
// Smem: A[m][k] / B^T[n][k], 128B rows, SW128 XOR swizzle, LDSM fragments.
// ---------------------------------------------------------------------------
__device__ __forceinline__ void gemm128x64(
    const float* __restrict__ A, int lda,
    const float* __restrict__ B, int ldb,
    const float* __restrict__ bias,
    float* __restrict__ C, int ldc, int K)
{
    __shared__ uint4 As4[128*8];   // [row 0..127][k-chunk 0..7] (16B chunks), chunk ^= row&7
    __shared__ uint4 Bs4[64*8];    // [n 0..63][k-chunk 0..7]

    const int t = threadIdx.x, lane = t & 31, warp = t >> 5;
    const int wm = warp >> 1, wn = warp & 1;
    const int g  = lane >> 2, tig = lane & 3;

    // loaders
    const int arow = t >> 1, acg = (t & 1) * 16;  // A: row, k-col base (4 float4)
    const int bn = t & 63, bkg = (t >> 6) * 8;    // B: n col, k base (8 scalars)

    const uint32_t as_base = s2u(As4);
    const uint32_t bs_base = s2u(Bs4);

    // LDSM per-lane rows (A-style addressing for both operands)
    const int a_row0 = wm*32 +      (lane & 15);
    const int a_row1 = wm*32 + 16 + (lane & 15);
    const int b_row0 = wn*32 +      (lane & 15);
    const int b_row1 = wn*32 + 16 + (lane & 15);
    const int csel   = lane >> 4;  // chunk select

    float acc[2][4][4];
    #pragma unroll
    for (int i = 0; i < 2; i++)
        #pragma unroll
        for (int j = 0; j < 4; j++)
            #pragma unroll
            for (int c = 0; c < 4; c++) acc[i][j][c] = 0.f;

    float4 a[4]; float bb[8];
    // prefetch tile 0
    #pragma unroll
    for (int j = 0; j < 4; j++)
        a[j] = *(const float4*)(A + (size_t)arow*lda + acg + 4*j);
    #pragma unroll
    for (int i = 0; i < 8; i++)
        bb[i] = B[(size_t)(bkg + i)*ldb + bn];

    // stage tile 0
    #pragma unroll
    for (int j = 0; j < 4; j++) {
        uint4 w = make_uint4(f2tf(a[j].x), f2tf(a[j].y), f2tf(a[j].z), f2tf(a[j].w));
        As4[arow*8 + (((acg>>2)+j) ^ (arow&7))] = w;
    }
    {
        uint4 w0 = make_uint4(f2tf(bb[0]), f2tf(bb[1]), f2tf(bb[2]), f2tf(bb[3]));
        uint4 w1 = make_uint4(f2tf(bb[4]), f2tf(bb[5]), f2tf(bb[6]), f2tf(bb[7]));
        Bs4[bn*8 + (((bkg>>2)  ) ^ (bn&7))] = w0;
        Bs4[bn*8 + (((bkg>>2)+1) ^ (bn&7))] = w1;
    }
    __syncthreads();

    const int iters = K / 32;
    for (int it = 1; it <= iters; it++) {
        if (it < iters) {
            #pragma unroll
            for (int j = 0; j < 4; j++)
                a[j] = *(const float4*)(A + (size_t)arow*lda + it*32 + acg + 4*j);
            #pragma unroll
            for (int i = 0; i < 8; i++)
                bb[i] = B[(size_t)(it*32 + bkg + i)*ldb + bn];
        }

        // compute on staged tile: 4 k8-steps
        #pragma unroll
        for (int s = 0; s < 4; s++) {
            const int cl = s*2 + csel;
            unsigned af[2][4], bf[2][4];
            ldsm4(af[0], as_base + (uint32_t)(a_row0*8 + (cl ^ (a_row0&7)))*16u);
            ldsm4(af[1], as_base + (uint32_t)(a_row1*8 + (cl ^ (a_row1&7)))*16u);
            ldsm4(bf[0], bs_base + (uint32_t)(b_row0*8 + (cl ^ (b_row0&7)))*16u);
            ldsm4(bf[1], bs_base + (uint32_t)(b_row1*8 + (cl ^ (b_row1&7)))*16u);
            #pragma unroll
            for (int mt = 0; mt < 2; mt++)
                #pragma unroll
                for (int nt = 0; nt < 4; nt++) {
                    unsigned b2[2] = { bf[nt>>1][nt&1], bf[nt>>1][(nt&1)|2] };
                    mma_tf32(acc[mt][nt], af[mt], b2);
                }
        }

        if (it < iters) {
            __syncthreads();
            #pragma unroll
            for (int j = 0; j < 4; j++) {
                uint4 w = make_uint4(f2tf(a[j].x), f2tf(a[j].y), f2tf(a[j].z), f2tf(a[j].w));
                As4[arow*8 + (((acg>>2)+j) ^ (arow&7))] = w;
            }
            uint4 w0 = make_uint4(f2tf(bb[0]), f2tf(bb[1]), f2tf(bb[2]), f2tf(bb[3]));
            uint4 w1 = make_uint4(f2tf(bb[4]), f2tf(bb[5]), f2tf(bb[6]), f2tf(bb[7]));
            Bs4[bn*8 + (((bkg>>2)  ) ^ (bn&7))] = w0;
            Bs4[bn*8 + (((bkg>>2)+1) ^ (bn&7))] = w1;
            __syncthreads();
        }
    }

    // epilogue
    #pragma unroll
    for (int mt = 0; mt < 2; mt++) {
        #pragma unroll
        for (int nt = 0; nt < 4; nt++) {
            const int row = wm*32 + mt*16 + g;
            const int col = wn*32 + nt*8 + 2*tig;
            const float b0 = bias[col], b1 = bias[col+1];
            *(float2*)(C + (size_t)row*ldc + col) =
                make_float2(acc[mt][nt][0] + b0, acc[mt][nt][1] + b1);
            *(float2*)(C + (size_t)(row+8)*ldc + col) =
                make_float2(acc[mt][nt][2] + b0, acc[mt][nt][3] + b1);
        }
    }
}

// ---------------------------------------------------------------------------
// QKV projection
// ---------------------------------------------------------------------------
__global__ __launch_bounds__(256) void qkv_kernel(
    const float* __restrict__ x,
    const float* __restrict__ Qw, const float* __restrict__ Qb,
    const float* __restrict__ Kw, const float* __restrict__ Kb,
    const float* __restrict__ Vw, const float* __restrict__ Vb)
{
    const int proj = blockIdx.y >> 4;
    const int h    = blockIdx.y & 15;

    const float* W; const float* bias; float* out;
    if (proj == 0)      { W = Qw; bias = Qb; out = g_q; }
    else if (proj == 1) { W = Kw; bias = Kb; out = g_k; }
    else                { W = Vw; bias = Vb; out = g_v; }

    const int rbase = blockIdx.x * 128;
    const int b     = rbase / SEQ;
    const int srow  = rbase % SEQ;

    gemm128x64(x + (size_t)rbase * DMODEL, DMODEL,
               W + (size_t)h * DMODEL * DHEAD, DHEAD,
               bias + h * DHEAD,
               out + (((size_t)(b*NH + h))*SEQ + srow) * DHEAD, DHEAD,
               DMODEL);
}

// ---------------------------------------------------------------------------
// Output projection
// ---------------------------------------------------------------------------
__global__ __launch_bounds__(256) void oproj_kernel(
    const float* __restrict__ Ow, const float* __restrict__ Ob,
    float* __restrict__ out)
{
    const int rbase = blockIdx.x * 128;
    const int nbase = blockIdx.y * 64;
    gemm128x64(g_att + (size_t)rbase * DMODEL, DMODEL,
               Ow + nbase, DMODEL,
               Ob + nbase,
               out + (size_t)rbase * DMODEL + nbase, DMODEL,
               DMODEL);
}

// ---------------------------------------------------------------------------
// Causal flash attention, tf32 mma + ldmatrix. Block = (64 q rows, one (b,h)).
// 8 warps: warp grid 4(M=16) x 2(N=32). Pitch-68 u32 rows (LDSM conflict-free).
// ---------------------------------------------------------------------------
#define PIT 68

__global__ __launch_bounds__(256) void attn_kernel()
{
    extern __shared__ unsigned smu[];
    unsigned* Qs  = smu;               // [q 0..63][d]   pre-scaled tf32
    unsigned* Ks  = Qs  + 64*PIT;      // [key][d]
    unsigned* Vst = Ks  + 64*PIT;      // [d][key]  (transposed)
    unsigned* Ps  = Vst + 64*PIT;      // [q][key]
    float* redM   = (float*)(Ps + 64*PIT);   // [2][64]
    float* redS   = redM + 128;              // [2][64]

    const int qt = (int)(gridDim.x - 1 - blockIdx.x);  // big tiles first
    const int bh = blockIdx.y;
    const int b  = bh >> 4;
    const int h  = bh & 15;

    const size_t base = (size_t)bh * SEQ * DHEAD;
    const float* Qp = g_q + base + (size_t)qt*64*DHEAD;
    const float* Kp = g_k + base;
    const float* Vp = g_v + base;

    const int t = threadIdx.x, lane = t & 31, warp = t >> 5;
    const int wm = warp >> 1, wn = warp & 1;
    const int g  = lane >> 2, tig = lane & 3;
    const int r_lo = wm*16 + g, r_hi = r_lo + 8;

    const uint32_t qs_b = s2u(Qs), ks_b = s2u(Ks), vs_b = s2u(Vst), ps_b = s2u(Ps);

    // LDSM per-lane rows
    const int m_row  = wm*16 +      (lane & 15);
    const int n_row0 = wn*32 +      (lane & 15);
    const int n_row1 = wn*32 + 16 + (lane & 15);
    const int ccol   = 4 * (lane >> 4);   // u32 col offset within k8

    // Load Q tile, pre-scaled by 1/sqrt(64)
    #pragma unroll
    for (int u = 0; u < 4; u++) {
        int idx = t + u*256;
        int row = idx >> 4, col = (idx & 15) * 4;
        float4 v = *(const float4*)(Qp + (size_t)row*DHEAD + col);
        uint4 w = make_uint4(f2tf(v.x*0.125f), f2tf(v.y*0.125f),
                             f2tf(v.z*0.125f), f2tf(v.w*0.125f));
        *(uint4*)&Qs[row*PIT + col] = w;
    }

    float m0 = -1e30f, m1 = -1e30f, l0 = 0.f, l1 = 0.f;
    float oacc[4][4];
    #pragma unroll
    for (int i = 0; i < 4; i++)
        #pragma unroll
        for (int j = 0; j < 4; j++) oacc[i][j] = 0.f;

    // V transpose loader indices: 4x4 block per thread
    const int vr4 = (t >> 4) * 4;   // key rows
    const int vc4 = (t & 15) * 4;   // d cols

    for (int kt = 0; kt <= qt; kt++) {
        __syncthreads();  // prev PV done; Q staged (first iter)

        const float* Kt = Kp + (size_t)kt*64*DHEAD;
        const float* Vt = Vp + (size_t)kt*64*DHEAD;
        // K: [key][d] straight
        #pragma unroll
        for (int u = 0; u < 4; u++) {
            int idx = t + u*256;
            int row = idx >> 4, col = (idx & 15) * 4;
            float4 kv = *(const float4*)(Kt + (size_t)row*DHEAD + col);
            uint4 w = make_uint4(f2tf(kv.x), f2tf(kv.y), f2tf(kv.z), f2tf(kv.w));
            *(uint4*)&Ks[row*PIT + col] = w;
        }
        // V: transpose into [d][key] via 4x4 blocks (vector loads + vector stores)
        {
            float4 rv[4];
            #pragma unroll
            for (int i = 0; i < 4; i++)
                rv[i] = *(const float4*)(Vt + (size_t)(vr4+i)*DHEAD + vc4);
            const float* fv = (const float*)rv;  // fv[i*4 + j]
            #pragma unroll
            for (int j = 0; j < 4; j++) {
                uint4 w = make_uint4(f2tf(fv[0*4+j]), f2tf(fv[1*4+j]),
                                     f2tf(fv[2*4+j]), f2tf(fv[3*4+j]));
                *(uint4*)&Vst[(vc4+j)*PIT + vr4] = w;
            }
        }
        __syncthreads();

        // S = Q * K^T  (m=64, n=64(keys), k=64(d))
        float sacc[4][4];
        #pragma unroll
        for (int i = 0; i < 4; i++)
            #pragma unroll
            for (int j = 0; j < 4; j++) sacc[i][j] = 0.f;

        #pragma unroll
        for (int s = 0; s < 8; s++) {
            const uint32_t cb = (uint32_t)(s*8 + ccol) * 4u;
            unsigned af[4], bf[2][4];
            ldsm4(af,    qs_b + (uint32_t)m_row*(PIT*4) + cb);
            ldsm4(bf[0], ks_b + (uint32_t)n_row0*(PIT*4) + cb);
            ldsm4(bf[1], ks_b + (uint32_t)n_row1*(PIT*4) + cb);
            #pragma unroll
            for (int nt = 0; nt < 4; nt++) {
                unsigned b2[2] = { bf[nt>>1][nt&1], bf[nt>>1][(nt&1)|2] };
                mma_tf32(sacc[nt], af, b2);
            }
        }

        // causal mask on diagonal tile (matches reference's -1e5)
        if (kt == qt) {
            #pragma unroll
            for (int nt = 0; nt < 4; nt++) {
                const int c = wn*32 + nt*8 + 2*tig;
                if (c     > r_lo) sacc[nt][0] = -100000.0f;
                if (c + 1 > r_lo) sacc[nt][1] = -100000.0f;
                if (c     > r_hi) sacc[nt][2] = -100000.0f;
                if (c + 1 > r_hi) sacc[nt][3] = -100000.0f;
            }
        }

        // row max: warp-partial via shfl, cross-warp via smem
        float pm0 = -1e30f, pm1 = -1e30f;
        #pragma unroll
        for (int nt = 0; nt < 4; nt++) {
            pm0 = fmaxf(pm0, fmaxf(sacc[nt][0], sacc[nt][1]));
            pm1 = fmaxf(pm1, fmaxf(sacc[nt][2], sacc[nt][3]));
        }
        pm0 = fmaxf(pm0, __shfl_xor_sync(0xffffffffu, pm0, 1));
        pm0 = fmaxf(pm0, __shfl_xor_sync(0xffffffffu, pm0, 2));
        pm1 = fmaxf(pm1, __shfl_xor_sync(0xffffffffu, pm1, 1));
        pm1 = fmaxf(pm1, __shfl_xor_sync(0xffffffffu, pm1, 2));
        if (tig == 0) { redM[wn*64 + r_lo] = pm0; redM[wn*64 + r_hi] = pm1; }
        __syncthreads();
        pm0 = fmaxf(pm0, redM[(wn^1)*64 + r_lo]);
        pm1 = fmaxf(pm1, redM[(wn^1)*64 + r_hi]);

        const float mn0 = fmaxf(m0, pm0), mn1 = fmaxf(m1, pm1);
        const float f0 = __expf(m0 - mn0), f1 = __expf(m1 - mn1);
        m0 = mn0; m1 = mn1;

        float ps0 = 0.f, ps1 = 0.f;
        #pragma unroll
        for (int nt = 0; nt < 4; nt++) {
            const float p0 = __expf(sacc[nt][0] - mn0);
            const float p1 = __expf(sacc[nt][1] - mn0);
            const float p2 = __expf(sacc[nt][2] - mn1);
            const float p3 = __expf(sacc[nt][3] - mn1);
            ps0 += p0 + p1; ps1 += p2 + p3;
            const int c = wn*32 + nt*8 + 2*tig;
            *(uint2*)&Ps[r_lo*PIT + c] = make_uint2(f2tf(p0), f2tf(p1));
            *(uint2*)&Ps[r_hi*PIT + c] = make_uint2(f2tf(p2), f2tf(p3));
            oacc[nt][0] *= f0; oacc[nt][1] *= f0;
            oacc[nt][2] *= f1; oacc[nt][3] *= f1;
        }
        ps0 += __shfl_xor_sync(0xffffffffu, ps0, 1);
        ps0 += __shfl_xor_sync(0xffffffffu, ps0, 2);
        ps1 += __shfl_xor_sync(0xffffffffu, ps1, 1);
        ps1 += __shfl_xor_sync(0xffffffffu, ps1, 2);
        if (tig == 0) { redS[wn*64 + r_lo] = ps0; redS[wn*64 + r_hi] = ps1; }
        __syncthreads();  // also guarantees Ps/Vst complete before PV mma
        ps0 += redS[(wn^1)*64 + r_lo];
        ps1 += redS[(wn^1)*64 + r_hi];
        l0 = l0*f0 + ps0;
        l1 = l1*f1 + ps1;

        // O += P * V  (m=64, n=64(d), k=64(keys))
        #pragma unroll
        for (int s = 0; s < 8; s++) {
            const uint32_t cb = (uint32_t)(s*8 + ccol) * 4u;
            unsigned af[4], bf[2][4];
            ldsm4(af,    ps_b + (uint32_t)m_row*(PIT*4) + cb);
            ldsm4(bf[0], vs_b + (uint32_t)n_row0*(PIT*4) + cb);
            ldsm4(bf[1], vs_b + (uint32_t)n_row1*(PIT*4) + cb);
            #pragma unroll
            for (int nt = 0; nt < 4; nt++) {
                unsigned b2[2] = { bf[nt>>1][nt&1], bf[nt>>1][(nt&1)|2] };
                mma_tf32(oacc[nt], af, b2);
            }
        }
    }

    // normalize + write g_att[(b*SEQ + s)*1024 + h*64 + d]
    const float inv0 = 1.0f / l0, inv1 = 1.0f / l1;
    float* outp = g_att + ((size_t)b*SEQ + (size_t)qt*64)*DMODEL + h*DHEAD;
    #pragma unroll
    for (int nt = 0; nt < 4; nt++) {
        const int c = wn*32 + nt*8 + 2*tig;
        *(float2*)(outp + (size_t)r_lo*DMODEL + c) =
            make_float2(oacc[nt][0]*inv0, oacc[nt][1]*inv0);
        *(float2*)(outp + (size_t)r_hi*DMODEL + c) =
            make_float2(oacc[nt][2]*inv1, oacc[nt][3]*inv1);
    }
}

extern "C" void kernel_launch(void* const* d_in, const int* in_sizes, int n_in,
                              void* d_out, int out_size)
{
    const float* x  = (const float*)d_in[0];
    const float* Qw = (const float*)d_in[1];
    const float* Qb = (const float*)d_in[2];
    const float* Kw = (const float*)d_in[3];
    const float* Kb = (const float*)d_in[4];
    const float* Vw = (const float*)d_in[5];
    const float* Vb = (const float*)d_in[6];
    const float* Ow = (const float*)d_in[7];
    const float* Ob = (const float*)d_in[8];
    float* out = (float*)d_out;

    // QKV projection: 64 m-tiles x 48 (proj,head)
    qkv_kernel<<<dim3(64, 48), 256>>>(x, Qw, Qb, Kw, Kb, Vw, Vb);

    // Flash attention: 32 q-tiles x 64 (b,h)
    const int smem = 4*64*PIT*4 + 2*128*4;  // 70656 B
    cudaFuncSetAttribute(attn_kernel,
                         cudaFuncAttributeMaxDynamicSharedMemorySize, smem);
    attn_kernel<<<dim3(32, 64), 256, smem>>>();

    // Output projection: 64 m-tiles x 16 n-tiles
    oproj_kernel<<<dim3(64, 16), 256>>>(Ow, Ob, out);
}

// round 5
// speedup vs baseline: 1.0194x; 1.0194x over previous
#include <cuda_runtime.h>
#include <stdint.h>
#include <math.h>

#define BATCH 4
#define SEQ   2048
#define NH    16
#define DHEAD 64
#define DMODEL 1024

// Scratch (allocation-free rule: __device__ globals)
__device__ float g_q[(size_t)BATCH*NH*SEQ*DHEAD];
__device__ float g_k[(size_t)BATCH*NH*SEQ*DHEAD];
__device__ float g_v[(size_t)BATCH*NH*SEQ*DHEAD];
__device__ float g_att[(size_t)BATCH*SEQ*DMODEL];

__device__ __forceinline__ unsigned f2tf(float f){
    unsigned u;
    asm("cvt.rna.tf32.f32 %0, %1;" : "=r"(u) : "f"(f));
    return u;
}

__device__ __forceinline__ uint32_t s2u(const void* p){
    return (uint32_t)__cvta_generic_to_shared(p);
}

__device__ __forceinline__ void ldsm4(unsigned r[4], uint32_t addr){
    asm volatile("ldmatrix.sync.aligned.m8n8.x4.shared.b16 {%0,%1,%2,%3}, [%4];"
        : "=r"(r[0]), "=r"(r[1]), "=r"(r[2]), "=r"(r[3]) : "r"(addr));
}

__device__ __forceinline__ void mma_tf32(float* d, const unsigned* a, const unsigned* b){
    asm volatile(
        "mma.sync.aligned.m16n8k8.row.col.f32.tf32.tf32.f32 "
        "{%0,%1,%2,%3},{%4,%5,%6,%7},{%8,%9},{%0,%1,%2,%3};\n"
        : "+f"(d[0]), "+f"(d[1]), "+f"(d[2]), "+f"(d[3])
        : "r"(a[0]), "r"(a[1]), "r"(a[2]), "r"(a[3]), "r"(b[0]), "r"(b[1]));
}

// ---------------------------------------------------------------------------
// tf32 GEMM core: C[128 x 64] = A[128 x K] * B[K x 64] + bias
// 256 threads, 8 warps (4m x 2n), warp tile 32x32, BK=32.
// DOUBLE-BUFFERED smem (1 barrier / k-iter), LDG prefetch overlapped
// with mma on the other stage. SW128 XOR swizzle + LDSM fragments.
// ---------------------------------------------------------------------------
#define AS_STRIDE (128*8)   // uint4 elems per A stage
#define BS_STRIDE (64*8)    // uint4 elems per B stage

__device__ __forceinline__ void gemm128x64(
    const float* __restrict__ A, int lda,
    const float* __restrict__ B, int ldb,
    const float* __restrict__ bias,
    float* __restrict__ C, int ldc, int K)
{
    extern __shared__ uint4 sm4[];
    uint4* As4 = sm4;                 // [2][128 rows][8 k-chunks], chunk ^= row&7
    uint4* Bs4 = sm4 + 2*AS_STRIDE;   // [2][64 n-rows][8 k-chunks]

    const int t = threadIdx.x, lane = t & 31, warp = t >> 5;
    const int wm = warp >> 1, wn = warp & 1;
    const int g  = lane >> 2, tig = lane & 3;

    // loaders
    const int arow = t >> 1, acg = (t & 1) * 16;  // A: row, k base (4 float4)
    const int bn = t & 63, bkg = (t >> 6) * 8;    // B: n col, k base (8 scalars)

    const uint32_t as_b = s2u(As4);
    const uint32_t bs_b = s2u(Bs4);

    const int a_row0 = wm*32 +      (lane & 15);
    const int a_row1 = wm*32 + 16 + (lane & 15);
    const int b_row0 = wn*32 +      (lane & 15);
    const int b_row1 = wn*32 + 16 + (lane & 15);
    const int csel   = lane >> 4;

    float acc[2][4][4];
    #pragma unroll
    for (int i = 0; i < 2; i++)
        #pragma unroll
        for (int j = 0; j < 4; j++)
            #pragma unroll
            for (int c = 0; c < 4; c++) acc[i][j][c] = 0.f;

    float4 a[4]; float bb[8];

    // prefetch + stage tile 0 into buffer 0
    #pragma unroll
    for (int j = 0; j < 4; j++)
        a[j] = *(const float4*)(A + (size_t)arow*lda + acg + 4*j);
    #pragma unroll
    for (int i = 0; i < 8; i++)
        bb[i] = B[(size_t)(bkg + i)*ldb + bn];

    #pragma unroll
    for (int j = 0; j < 4; j++) {
        uint4 w = make_uint4(f2tf(a[j].x), f2tf(a[j].y), f2tf(a[j].z), f2tf(a[j].w));
        As4[arow*8 + (((acg>>2)+j) ^ (arow&7))] = w;
    }
    {
        uint4 w0 = make_uint4(f2tf(bb[0]), f2tf(bb[1]), f2tf(bb[2]), f2tf(bb[3]));
        uint4 w1 = make_uint4(f2tf(bb[4]), f2tf(bb[5]), f2tf(bb[6]), f2tf(bb[7]));
        Bs4[bn*8 + (((bkg>>2)  ) ^ (bn&7))] = w0;
        Bs4[bn*8 + (((bkg>>2)+1) ^ (bn&7))] = w1;
    }
    __syncthreads();

    const int iters = K / 32;
    for (int it = 0; it < iters; it++) {
        const int cur = it & 1;
        const bool more = (it + 1 < iters);

        if (more) {
            #pragma unroll
            for (int j = 0; j < 4; j++)
                a[j] = *(const float4*)(A + (size_t)arow*lda + (it+1)*32 + acg + 4*j);
            #pragma unroll
            for (int i = 0; i < 8; i++)
                bb[i] = B[(size_t)((it+1)*32 + bkg + i)*ldb + bn];
        }

        // compute on staged tile (stage cur)
        const uint32_t as_s = as_b + (uint32_t)cur * (AS_STRIDE*16u);
        const uint32_t bs_s = bs_b + (uint32_t)cur * (BS_STRIDE*16u);
        #pragma unroll
        for (int s = 0; s < 4; s++) {
            const int cl = s*2 + csel;
            unsigned af[2][4], bf[2][4];
            ldsm4(af[0], as_s + (uint32_t)(a_row0*8 + (cl ^ (a_row0&7)))*16u);
            ldsm4(af[1], as_s + (uint32_t)(a_row1*8 + (cl ^ (a_row1&7)))*16u);
            ldsm4(bf[0], bs_s + (uint32_t)(b_row0*8 + (cl ^ (b_row0&7)))*16u);
            ldsm4(bf[1], bs_s + (uint32_t)(b_row1*8 + (cl ^ (b_row1&7)))*16u);
            #pragma unroll
            for (int mt = 0; mt < 2; mt++)
                #pragma unroll
                for (int nt = 0; nt < 4; nt++) {
                    unsigned b2[2] = { bf[nt>>1][nt&1], bf[nt>>1][(nt&1)|2] };
                    mma_tf32(acc[mt][nt], af[mt], b2);
                }
        }

        if (more) {
            const int nxt = (it + 1) & 1;
            uint4* Asn = As4 + nxt*AS_STRIDE;
            uint4* Bsn = Bs4 + nxt*BS_STRIDE;
            #pragma unroll
            for (int j = 0; j < 4; j++) {
                uint4 w = make_uint4(f2tf(a[j].x), f2tf(a[j].y), f2tf(a[j].z), f2tf(a[j].w));
                Asn[arow*8 + (((acg>>2)+j) ^ (arow&7))] = w;
            }
            uint4 w0 = make_uint4(f2tf(bb[0]), f2tf(bb[1]), f2tf(bb[2]), f2tf(bb[3]));
            uint4 w1 = make_uint4(f2tf(bb[4]), f2tf(bb[5]), f2tf(bb[6]), f2tf(bb[7]));
            Bsn[bn*8 + (((bkg>>2)  ) ^ (bn&7))] = w0;
            Bsn[bn*8 + (((bkg>>2)+1) ^ (bn&7))] = w1;
            __syncthreads();
        }
    }

    // epilogue
    #pragma unroll
    for (int mt = 0; mt < 2; mt++) {
        #pragma unroll
        for (int nt = 0; nt < 4; nt++) {
            const int row = wm*32 + mt*16 + g;
            const int col = wn*32 + nt*8 + 2*tig;
            const float b0 = bias[col], b1 = bias[col+1];
            *(float2*)(C + (size_t)row*ldc + col) =
                make_float2(acc[mt][nt][0] + b0, acc[mt][nt][1] + b1);
            *(float2*)(C + (size_t)(row+8)*ldc + col) =
                make_float2(acc[mt][nt][2] + b0, acc[mt][nt][3] + b1);
        }
    }
}

#define GEMM_SMEM ((2*AS_STRIDE + 2*BS_STRIDE) * 16)   // 49152 B

// ---------------------------------------------------------------------------
// QKV projection
// ---------------------------------------------------------------------------
__global__ __launch_bounds__(256, 2) void qkv_kernel(
    const float* __restrict__ x,
    const float* __restrict__ Qw, const float* __restrict__ Qb,
    const float* __restrict__ Kw, const float* __restrict__ Kb,
    const float* __restrict__ Vw, const float* __restrict__ Vb)
{
    const int proj = blockIdx.y >> 4;
    const int h    = blockIdx.y & 15;

    const float* W; const float* bias; float* out;
    if (proj == 0)      { W = Qw; bias = Qb; out = g_q; }
    else if (proj == 1) { W = Kw; bias = Kb; out = g_k; }
    else                { W = Vw; bias = Vb; out = g_v; }

    const int rbase = blockIdx.x * 128;
    const int b     = rbase / SEQ;
    const int srow  = rbase % SEQ;

    gemm128x64(x + (size_t)rbase * DMODEL, DMODEL,
               W + (size_t)h * DMODEL * DHEAD, DHEAD,
               bias + h * DHEAD,
               out + (((size_t)(b*NH + h))*SEQ + srow) * DHEAD, DHEAD,
               DMODEL);
}

// ---------------------------------------------------------------------------
// Output projection
// ---------------------------------------------------------------------------
__global__ __launch_bounds__(256, 2) void oproj_kernel(
    const float* __restrict__ Ow, const float* __restrict__ Ob,
    float* __restrict__ out)
{
    const int rbase = blockIdx.x * 128;
    const int nbase = blockIdx.y * 64;
    gemm128x64(g_att + (size_t)rbase * DMODEL, DMODEL,
               Ow + nbase, DMODEL,
               Ob + nbase,
               out + (size_t)rbase * DMODEL + nbase, DMODEL,
               DMODEL);
}

// ---------------------------------------------------------------------------
// Causal flash attention, tf32 mma + ldmatrix, pipelined K/V (double buffer).
// Block = (64 q rows, one (b,h)). 8 warps (4m x 2n). Pitch-68 u32 rows.
// ---------------------------------------------------------------------------
#define PIT 68
#define TILE_U32 (64*PIT)

__global__ __launch_bounds__(256, 2) void attn_kernel()
{
    extern __shared__ unsigned smu[];
    unsigned* Qs  = smu;                  // [q][d]      pre-scaled tf32
    unsigned* Ks  = Qs  + TILE_U32;       // [2][key][d]
    unsigned* Vst = Ks  + 2*TILE_U32;     // [2][d][key] (transposed)
    unsigned* Ps  = Vst + 2*TILE_U32;     // [q][key]
    float* redM   = (float*)(Ps + TILE_U32);   // [2][64]
    float* redS   = redM + 128;                // [2][64]

    const int qt = (int)(gridDim.x - 1 - blockIdx.x);  // big tiles first
    const int bh = blockIdx.y;
    const int b  = bh >> 4;
    const int h  = bh & 15;

    const size_t base = (size_t)bh * SEQ * DHEAD;
    const float* Qp = g_q + base + (size_t)qt*64*DHEAD;
    const float* Kp = g_k + base;
    const float* Vp = g_v + base;

    const int t = threadIdx.x, lane = t & 31, warp = t >> 5;
    const int wm = warp >> 1, wn = warp & 1;
    const int g  = lane >> 2, tig = lane & 3;
    const int r_lo = wm*16 + g, r_hi = r_lo + 8;

    const uint32_t qs_b = s2u(Qs), ks_b = s2u(Ks), vs_b = s2u(Vst), ps_b = s2u(Ps);

    const int m_row  = wm*16 +      (lane & 15);
    const int n_row0 = wn*32 +      (lane & 15);
    const int n_row1 = wn*32 + 16 + (lane & 15);
    const int ccol   = 4 * (lane >> 4);

    // loader indices
    const int krow = t >> 4, kcol = (t & 15) * 4;   // K: 4 rows per thread (stride 16)
    const int vr4 = (t >> 4) * 4, vc4 = (t & 15) * 4; // V: 4x4 transpose block

    // Load Q tile, pre-scaled by 1/sqrt(64)
    #pragma unroll
    for (int u = 0; u < 4; u++) {
        const int row = krow + u*16;
        float4 v = *(const float4*)(Qp + (size_t)row*DHEAD + kcol);
        uint4 w = make_uint4(f2tf(v.x*0.125f), f2tf(v.y*0.125f),
                             f2tf(v.z*0.125f), f2tf(v.w*0.125f));
        *(uint4*)&Qs[row*PIT + kcol] = w;
    }
    // Preload K/V tile 0 into stage 0
    {
        #pragma unroll
        for (int u = 0; u < 4; u++) {
            const int row = krow + u*16;
            float4 kv = *(const float4*)(Kp + (size_t)row*DHEAD + kcol);
            uint4 w = make_uint4(f2tf(kv.x), f2tf(kv.y), f2tf(kv.z), f2tf(kv.w));
            *(uint4*)&Ks[row*PIT + kcol] = w;
        }
        float4 rv[4];
        #pragma unroll
        for (int i = 0; i < 4; i++)
            rv[i] = *(const float4*)(Vp + (size_t)(vr4+i)*DHEAD + vc4);
        const float* fv = (const float*)rv;
        #pragma unroll
        for (int j = 0; j < 4; j++) {
            uint4 w = make_uint4(f2tf(fv[0*4+j]), f2tf(fv[1*4+j]),
                                 f2tf(fv[2*4+j]), f2tf(fv[3*4+j]));
            *(uint4*)&Vst[(vc4+j)*PIT + vr4] = w;
        }
    }

    float m0 = -1e30f, m1 = -1e30f, l0 = 0.f, l1 = 0.f;
    float oacc[4][4];
    #pragma unroll
    for (int i = 0; i < 4; i++)
        #pragma unroll
        for (int j = 0; j < 4; j++) oacc[i][j] = 0.f;

    for (int kt = 0; kt <= qt; kt++) {
        __syncthreads();   // stage(cur) K/V + Q (first iter) visible; prev PV done
        const int cur = kt & 1;
        const bool more = (kt < qt);

        // issue global loads for next K/V tile (latency hidden under S-mma+softmax)
        float4 kpre[4], vpre[4];
        if (more) {
            const float* Kn = Kp + (size_t)(kt+1)*64*DHEAD;
            const float* Vn = Vp + (size_t)(kt+1)*64*DHEAD;
            #pragma unroll
            for (int u = 0; u < 4; u++)
                kpre[u] = *(const float4*)(Kn + (size_t)(krow + u*16)*DHEAD + kcol);
            #pragma unroll
            for (int i = 0; i < 4; i++)
                vpre[i] = *(const float4*)(Vn + (size_t)(vr4+i)*DHEAD + vc4);
        }

        const uint32_t ks_s = ks_b + (uint32_t)cur * (TILE_U32*4u);
        const uint32_t vs_s = vs_b + (uint32_t)cur * (TILE_U32*4u);

        // S = Q * K^T  (m=64, n=64 keys, k=64 d)
        float sacc[4][4];
        #pragma unroll
        for (int i = 0; i < 4; i++)
            #pragma unroll
            for (int j = 0; j < 4; j++) sacc[i][j] = 0.f;

        #pragma unroll
        for (int s = 0; s < 8; s++) {
            const uint32_t cb = (uint32_t)(s*8 + ccol) * 4u;
            unsigned af[4], bf[2][4];
            ldsm4(af,    qs_b + (uint32_t)m_row*(PIT*4) + cb);
            ldsm4(bf[0], ks_s + (uint32_t)n_row0*(PIT*4) + cb);
            ldsm4(bf[1], ks_s + (uint32_t)n_row1*(PIT*4) + cb);
            #pragma unroll
            for (int nt = 0; nt < 4; nt++) {
                unsigned b2[2] = { bf[nt>>1][nt&1], bf[nt>>1][(nt&1)|2] };
                mma_tf32(sacc[nt], af, b2);
            }
        }

        // causal mask on diagonal tile (reference uses -1e5)
        if (kt == qt) {
            #pragma unroll
            for (int nt = 0; nt < 4; nt++) {
                const int c = wn*32 + nt*8 + 2*tig;
                if (c     > r_lo) sacc[nt][0] = -100000.0f;
                if (c + 1 > r_lo) sacc[nt][1] = -100000.0f;
                if (c     > r_hi) sacc[nt][2] = -100000.0f;
                if (c + 1 > r_hi) sacc[nt][3] = -100000.0f;
            }
        }

        // row max: warp-partial via shfl, cross-warp via smem
        float pm0 = -1e30f, pm1 = -1e30f;
        #pragma unroll
        for (int nt = 0; nt < 4; nt++) {
            pm0 = fmaxf(pm0, fmaxf(sacc[nt][0], sacc[nt][1]));
            pm1 = fmaxf(pm1, fmaxf(sacc[nt][2], sacc[nt][3]));
        }
        pm0 = fmaxf(pm0, __shfl_xor_sync(0xffffffffu, pm0, 1));
        pm0 = fmaxf(pm0, __shfl_xor_sync(0xffffffffu, pm0, 2));
        pm1 = fmaxf(pm1, __shfl_xor_sync(0xffffffffu, pm1, 1));
        pm1 = fmaxf(pm1, __shfl_xor_sync(0xffffffffu, pm1, 2));
        if (tig == 0) { redM[wn*64 + r_lo] = pm0; redM[wn*64 + r_hi] = pm1; }
        __syncthreads();
        pm0 = fmaxf(pm0, redM[(wn^1)*64 + r_lo]);
        pm1 = fmaxf(pm1, redM[(wn^1)*64 + r_hi]);

        const float mn0 = fmaxf(m0, pm0), mn1 = fmaxf(m1, pm1);
        const float f0 = __expf(m0 - mn0), f1 = __expf(m1 - mn1);
        m0 = mn0; m1 = mn1;

        float ps0 = 0.f, ps1 = 0.f;
        #pragma unroll
        for (int nt = 0; nt < 4; nt++) {
            const float p0 = __expf(sacc[nt][0] - mn0);
            const float p1 = __expf(sacc[nt][1] - mn0);
            const float p2 = __expf(sacc[nt][2] - mn1);
            const float p3 = __expf(sacc[nt][3] - mn1);
            ps0 += p0 + p1; ps1 += p2 + p3;
            const int c = wn*32 + nt*8 + 2*tig;
            *(uint2*)&Ps[r_lo*PIT + c] = make_uint2(f2tf(p0), f2tf(p1));
            *(uint2*)&Ps[r_hi*PIT + c] = make_uint2(f2tf(p2), f2tf(p3));
            oacc[nt][0] *= f0; oacc[nt][1] *= f0;
            oacc[nt][2] *= f1; oacc[nt][3] *= f1;
        }
        ps0 += __shfl_xor_sync(0xffffffffu, ps0, 1);
        ps0 += __shfl_xor_sync(0xffffffffu, ps0, 2);
        ps1 += __shfl_xor_sync(0xffffffffu, ps1, 1);
        ps1 += __shfl_xor_sync(0xffffffffu, ps1, 2);
        if (tig == 0) { redS[wn*64 + r_lo] = ps0; redS[wn*64 + r_hi] = ps1; }
        __syncthreads();   // Ps complete before PV; red ready
        ps0 += redS[(wn^1)*64 + r_lo];
        ps1 += redS[(wn^1)*64 + r_hi];
        l0 = l0*f0 + ps0;
        l1 = l1*f1 + ps1;

        // stage next K/V into alternate buffers (prev PV already drained by
        // this iter's loop-top barrier; next iter's top barrier publishes)
        if (more) {
            const int nxt = cur ^ 1;
            unsigned* Kn = Ks  + nxt*TILE_U32;
            unsigned* Vn = Vst + nxt*TILE_U32;
            #pragma unroll
            for (int u = 0; u < 4; u++) {
                const int row = krow + u*16;
                uint4 w = make_uint4(f2tf(kpre[u].x), f2tf(kpre[u].y),
                                     f2tf(kpre[u].z), f2tf(kpre[u].w));
                *(uint4*)&Kn[row*PIT + kcol] = w;
            }
            const float* fv = (const float*)vpre;
            #pragma unroll
            for (int j = 0; j < 4; j++) {
                uint4 w = make_uint4(f2tf(fv[0*4+j]), f2tf(fv[1*4+j]),
                                     f2tf(fv[2*4+j]), f2tf(fv[3*4+j]));
                *(uint4*)&Vn[(vc4+j)*PIT + vr4] = w;
            }
        }

        // O += P * V  (m=64, n=64 d, k=64 keys)
        #pragma unroll
        for (int s = 0; s < 8; s++) {
            const uint32_t cb = (uint32_t)(s*8 + ccol) * 4u;
            unsigned af[4], bf[2][4];
            ldsm4(af,    ps_b + (uint32_t)m_row*(PIT*4) + cb);
            ldsm4(bf[0], vs_s + (uint32_t)n_row0*(PIT*4) + cb);
            ldsm4(bf[1], vs_s + (uint32_t)n_row1*(PIT*4) + cb);
            #pragma unroll
            for (int nt = 0; nt < 4; nt++) {
                unsigned b2[2] = { bf[nt>>1][nt&1], bf[nt>>1][(nt&1)|2] };
                mma_tf32(oacc[nt], af, b2);
            }
        }
    }

    // normalize + write g_att[(b*SEQ + s)*1024 + h*64 + d]
    const float inv0 = 1.0f / l0, inv1 = 1.0f / l1;
    float* outp = g_att + ((size_t)b*SEQ + (size_t)qt*64)*DMODEL + h*DHEAD;
    #pragma unroll
    for (int nt = 0; nt < 4; nt++) {
        const int c = wn*32 + nt*8 + 2*tig;
        *(float2*)(outp + (size_t)r_lo*DMODEL + c) =
            make_float2(oacc[nt][0]*inv0, oacc[nt][1]*inv0);
        *(float2*)(outp + (size_t)r_hi*DMODEL + c) =
            make_float2(oacc[nt][2]*inv1, oacc[nt][3]*inv1);
    }
}

extern "C" void kernel_launch(void* const* d_in, const int* in_sizes, int n_in,
                              void* d_out, int out_size)
{
    const float* x  = (const float*)d_in[0];
    const float* Qw = (const float*)d_in[1];
    const float* Qb = (const float*)d_in[2];
    const float* Kw = (const float*)d_in[3];
    const float* Kb = (const float*)d_in[4];
    const float* Vw = (const float*)d_in[5];
    const float* Vb = (const float*)d_in[6];
    const float* Ow = (const float*)d_in[7];
    const float* Ob = (const float*)d_in[8];
    float* out = (float*)d_out;

    cudaFuncSetAttribute(qkv_kernel,
                         cudaFuncAttributeMaxDynamicSharedMemorySize, GEMM_SMEM);
    cudaFuncSetAttribute(oproj_kernel,
                         cudaFuncAttributeMaxDynamicSharedMemorySize, GEMM_SMEM);

    // QKV projection: 64 m-tiles x 48 (proj,head)
    qkv_kernel<<<dim3(64, 48), 256, GEMM_SMEM>>>(x, Qw, Qb, Kw, Kb, Vw, Vb);

    // Flash attention: 32 q-tiles x 64 (b,h)
    const int attn_smem = 6*TILE_U32*4 + 2*128*4;  // 105472 B
    cudaFuncSetAttribute(attn_kernel,
                         cudaFuncAttributeMaxDynamicSharedMemorySize, attn_smem);
    attn_kernel<<<dim3(32, 64), 256, attn_smem>>>();

    // Output projection: 64 m-tiles x 16 n-tiles
    oproj_kernel<<<dim3(64, 16), 256, GEMM_SMEM>>>(Ow, Ob, out);
}